// round 15
// baseline (speedup 1.0000x reference)
#include <cuda_runtime.h>
#include <cstdint>

#define BB 16
#define SS 4096
#define FF 256
#define KK 512
#define PP 8
#define NITS 5
#define THREADS 512
#define BPB 8                 // blocks per batch
#define GRID (BB * BPB)       // 128
#define NCB 64                // centroids per block (topk)
#define TPC 8                 // threads per centroid in topk
#define FIXSCALE 1099511627776.0   // 2^40
#define NC 6
#define NCELLS 216
#define H2MARG 0.0276778f     // (1/6)^2 - 1e-4 safety margin

typedef unsigned long long u64;
typedef unsigned short u16;

// ---------------- device scratch ----------------
static __device__ u64 g_isum[3][BB * KK * 3];   // triple-buffered fixed-point sums
static __device__ int g_icnt[3][BB * KK];       // triple-buffered counts
static __device__ int g_sidx[BB * KK][PP];      // final top-8 indices per centroid

struct Bar { unsigned cnt; unsigned phase; unsigned pad[30]; };  // 128B, own line
static __device__ Bar g_bars[BB];

// ---------------- dynamic smem layout ----------------
struct SP {
    float4 tp[SS];        // 64KB: batch points, cell-sorted (persistent)
    u16 tpi[SS];          // 8KB: original s of sorted point (persistent)
    int startP[257];      // point-cell starts (persistent)
    int wsums[8];         // scan scratch
    int cut[BPB + 1];     // cell-aligned block slice cuts
    union {
        struct {          // assign phase (~11KB)
            float4 sc[KK];      // cell-sorted centroids
            u16 sk[KK];         // original k
            int cntC[256];      // counters / cursors
            int startC[257];
        } a;
        struct {          // topk phase (~33KB)
            u64 part[NCB][TPC][PP];
            int fblist[NCB];
            int fbn;
        } t;
    } u;
};

// ---------------- FP helpers (reference-exact semantics) --------
__device__ __forceinline__ unsigned float_ord(float f) {
    unsigned u = __float_as_uint(f);
    return (u & 0x80000000u) ? ~u : (u | 0x80000000u);
}
__device__ __forceinline__ float ord_inv(unsigned u) {
    return __uint_as_float((u & 0x80000000u) ? (u & 0x7FFFFFFFu) : ~u);
}
__device__ __forceinline__ u64 umin64(u64 a, u64 b) { return a < b ? a : b; }
// mirrors jnp.sum(a*a,-1): elementwise mul then sequential reduce (no FMA contraction)
__device__ __forceinline__ float norm3_nofma(float a0, float a1, float a2) {
    return __fadd_rn(__fadd_rn(__fmul_rn(a0, a0), __fmul_rn(a1, a1)), __fmul_rn(a2, a2));
}
// ascending-d fma chain
__device__ __forceinline__ float dot3_fma(float a0, float a1, float a2,
                                          float b0, float b1, float b2) {
    return __fmaf_rn(a2, b2, __fmaf_rn(a1, b1, __fmul_rn(a0, b0)));
}
// (aa - 2*dot) + bb, reference grouping
__device__ __forceinline__ float sqdist_combine(float aa, float dot, float bb) {
    return __fadd_rn(__fmaf_rn(-2.0f, dot, aa), bb);
}
__device__ __forceinline__ int cellc(float x) {
    int i = (int)floorf(x * 6.0f);
    return i < 0 ? 0 : (i > 5 ? 5 : i);
}

__device__ __forceinline__ void sort8_bitonic(u64 v[8]) {
#define CSWP(i, j) { u64 lo = umin64(v[i], v[j]); \
                     u64 hi = (v[i] < v[j]) ? v[j] : v[i]; \
                     v[i] = lo; v[j] = hi; }
    CSWP(0, 4) CSWP(1, 5) CSWP(2, 6) CSWP(3, 7)
    CSWP(0, 2) CSWP(1, 3) CSWP(4, 6) CSWP(5, 7)
    CSWP(0, 1) CSWP(2, 3) CSWP(4, 5) CSWP(6, 7)
#undef CSWP
}
__device__ __forceinline__ void merge8(u64 a[8], const u64 b[8]) {
    u64 m[8];
#pragma unroll
    for (int i = 0; i < 8; i++) m[i] = umin64(a[i], b[7 - i]);
    sort8_bitonic(m);
#pragma unroll
    for (int i = 0; i < 8; i++) a[i] = m[i];
}

// sorted-insert; <= lets equal-dist smaller-idx keys reach the key compare
__device__ __forceinline__ void top8_insert(u64 l[PP], float& thresh, float v, unsigned idx) {
    if (v <= thresh) {
        float vc = (v == 0.0f) ? 0.0f : v;   // canonicalize -0.0
        u64 key = ((u64)float_ord(vc) << 32) | idx;
        if (key < l[7]) {
            l[7] = key;
#pragma unroll
            for (int j = 7; j > 0; --j)
                if (l[j] < l[j - 1]) { u64 tt = l[j]; l[j] = l[j - 1]; l[j - 1] = tt; }
            thresh = ord_inv((unsigned)(l[7] >> 32));
        }
    }
}

// shfl-based 256-entry scan: counts in cnt[] -> starts in startArr[0..256],
// exclusive cursors written back into cnt[].
__device__ __forceinline__ void scan256(int* cnt, int* startArr, int* wsums, int tid) {
    int w = tid >> 5, lane = tid & 31;
    int orig = 0, v = 0;
    if (tid < 256) {
        orig = cnt[tid]; v = orig;
#pragma unroll
        for (int off = 1; off < 32; off <<= 1) {
            int n = __shfl_up_sync(0xFFFFFFFFu, v, off);
            if (lane >= off) v += n;
        }
        if (lane == 31) wsums[w] = v;
    }
    __syncthreads();
    if (tid < 8) {
        int s = wsums[tid];
#pragma unroll
        for (int off = 1; off < 8; off <<= 1) {
            int n = __shfl_up_sync(0xFFu, s, off);
            if (tid >= off) s += n;
        }
        wsums[tid] = s;
    }
    __syncthreads();
    if (tid < 256) {
        int incl = v + (w > 0 ? wsums[w - 1] : 0);
        startArr[tid + 1] = incl;
        cnt[tid] = incl - orig;       // exclusive prefix = scatter cursor
    }
    if (tid == 0) startArr[0] = 0;
    __syncthreads();
}

// ---------------- per-batch barrier (BPB blocks, all co-resident) ----
__device__ __forceinline__ void batch_sync(int b) {
    __syncthreads();
    if (threadIdx.x == 0) {
        __threadfence();
        unsigned gen = atomicAdd(&g_bars[b].phase, 0u);
        if (atomicAdd(&g_bars[b].cnt, 1u) == BPB - 1) {
            g_bars[b].cnt = 0;
            __threadfence();
            atomicAdd(&g_bars[b].phase, 1u);  // release
        } else {
            while (atomicAdd(&g_bars[b].phase, 0u) == gen) __nanosleep(32);
        }
        __threadfence();
    }
    __syncthreads();
}

__device__ __forceinline__ void load_centroid(int fb, int b, int k,
                                              float& c0, float& c1, float& c2) {
    int slot = b * KK + k;
    float cnt = (float)g_icnt[fb][slot];
    cnt = cnt > 1.0f ? cnt : 1.0f;
    c0 = __fdiv_rn((float)((double)(long long)g_isum[fb][3 * slot + 0] * (1.0 / FIXSCALE)), cnt);
    c1 = __fdiv_rn((float)((double)(long long)g_isum[fb][3 * slot + 1] * (1.0 / FIXSCALE)), cnt);
    c2 = __fdiv_rn((float)((double)(long long)g_isum[fb][3 * slot + 2] * (1.0 / FIXSCALE)), cnt);
}

// ---------------- megakernel: kmeans + topk (no gather) ----------------
__global__ void __launch_bounds__(THREADS, 1)
mega(const float* __restrict__ pos) {
    extern __shared__ char smem_raw[];
    SP* sp = reinterpret_cast<SP*>(smem_raw);

    const int tid = threadIdx.x;
    const int blk = blockIdx.x;
    const int b = blk / BPB;           // batch
    const int grp = blk % BPB;         // group within batch

    // ---- init: zero buffer 1, batch-local (this block's 64 slots) ----
    if (tid < NCB) {
        int slot = b * KK + grp * NCB + tid;
        g_icnt[1][slot] = 0;
        g_isum[1][3 * slot + 0] = 0ull;
        g_isum[1][3 * slot + 1] = 0ull;
        g_isum[1][3 * slot + 2] = 0ull;
    }

    // ---- bin ALL 4096 batch points by cell, once (persistent tp/tpi/startP) ----
    if (tid < 256) sp->u.a.cntC[tid] = 0;
    __syncthreads();
#pragma unroll
    for (int j = 0; j < 8; j++) {
        int i = j * 512 + tid;
        const float* qp = pos + ((size_t)b * SS + i) * 3;
        int cell = (cellc(qp[2]) * NC + cellc(qp[1])) * NC + cellc(qp[0]);
        atomicAdd(&sp->u.a.cntC[cell], 1);
    }
    __syncthreads();
    scan256(sp->u.a.cntC, sp->startP, sp->wsums, tid);
#pragma unroll
    for (int j = 0; j < 8; j++) {
        int i = j * 512 + tid;
        const float* qp = pos + ((size_t)b * SS + i) * 3;
        float q0 = qp[0], q1 = qp[1], q2 = qp[2];
        int cell = (cellc(q2) * NC + cellc(q1)) * NC + cellc(q0);
        int slot = atomicAdd(&sp->u.a.cntC[cell], 1);
        sp->tp[slot] = make_float4(q0, q1, q2, norm3_nofma(q0, q1, q2));
        sp->tpi[slot] = (u16)i;
    }
    __syncthreads();
    // cell-aligned block cuts: cut[g] = startP[min{c : startP[c] >= g*512}]
    if (tid < BPB + 1) {
        int target = tid * (SS / BPB);
        int c = 0;
        while (c < NCELLS && sp->startP[c] < target) c++;
        sp->cut[tid] = sp->startP[c];
    }
    batch_sync(b);   // covers init-zero + cuts (all batch-local)

    // ================= K-MEANS: 5 iterations, one batch barrier each =========
    for (int it = 0; it < NITS; it++) {
        const int Rb = it % 3;
        const int Wb = (it + 1) % 3;
        const int Zb = (it + 2) % 3;

        // centroid k = tid
        float c0, c1, c2;
        if (it == 0) {
            const float* cp = pos + ((size_t)b * SS + tid) * 3;
            c0 = cp[0]; c1 = cp[1]; c2 = cp[2];
        } else {
            load_centroid(Rb, b, tid, c0, c1, c2);
        }
        const float cn = norm3_nofma(c0, c1, c2);
        const int ccell = (cellc(c2) * NC + cellc(c1)) * NC + cellc(c0);

        if (tid < 256) sp->u.a.cntC[tid] = 0;
        if (tid < NCB) {          // zero Z-buffer slice (batch-local)
            int slot = b * KK + grp * NCB + tid;
            g_icnt[Zb][slot] = 0;
            g_isum[Zb][3 * slot + 0] = 0ull;
            g_isum[Zb][3 * slot + 1] = 0ull;
            g_isum[Zb][3 * slot + 2] = 0ull;
        }
        __syncthreads();
        atomicAdd(&sp->u.a.cntC[ccell], 1);
        __syncthreads();
        scan256(sp->u.a.cntC, sp->u.a.startC, sp->wsums, tid);
        {
            int slot = atomicAdd(&sp->u.a.cntC[ccell], 1);
            sp->u.a.sc[slot] = make_float4(c0, c1, c2, cn);
            sp->u.a.sk[slot] = (u16)tid;
        }
        __syncthreads();

        // ---- assign over this block's cell-aligned slice of sorted points ----
        for (int idx = sp->cut[grp] + tid; idx < sp->cut[grp + 1]; idx += THREADS) {
            float4 pt = sp->tp[idx];
            const float p0 = pt.x, p1 = pt.y, p2 = pt.z, pn = pt.w;
            const int pix = cellc(p0), piy = cellc(p1), piz = cellc(p2);
            const int xlo = pix > 0 ? pix - 1 : 0, xhi = pix < 5 ? pix + 1 : 5;
            const int ylo = piy > 0 ? piy - 1 : 0, yhi = piy < 5 ? piy + 1 : 5;
            const int zlo = piz > 0 ? piz - 1 : 0, zhi = piz < 5 ? piz + 1 : 5;

            u64 bkey = 0xFFFFFFFFFFFFFFFFull;
            for (int z = zlo; z <= zhi; z++) {
                for (int y = ylo; y <= yhi; y++) {
                    int row = (z * NC + y) * NC;
                    int t0 = sp->u.a.startC[row + xlo];
                    int t1 = sp->u.a.startC[row + xhi + 1];
                    int t = t0;
                    for (; t + 1 < t1; t += 2) {      // two independent chains
                        float4 ca = sp->u.a.sc[t];
                        float4 cb = sp->u.a.sc[t + 1];
                        float da = dot3_fma(p0, p1, p2, ca.x, ca.y, ca.z);
                        float db = dot3_fma(p0, p1, p2, cb.x, cb.y, cb.z);
                        float va = sqdist_combine(pn, da, ca.w);
                        float vb = sqdist_combine(pn, db, cb.w);
                        u64 ka = ((u64)float_ord(va) << 32) | sp->u.a.sk[t];
                        u64 kb = ((u64)float_ord(vb) << 32) | sp->u.a.sk[t + 1];
                        bkey = umin64(bkey, umin64(ka, kb));
                    }
                    if (t < t1) {
                        float4 c = sp->u.a.sc[t];
                        float dot = dot3_fma(p0, p1, p2, c.x, c.y, c.z);
                        float v = sqdist_combine(pn, dot, c.w);
                        bkey = umin64(bkey, ((u64)float_ord(v) << 32) | sp->u.a.sk[t]);
                    }
                }
            }
            {
                float bestv = ord_inv((unsigned)(bkey >> 32));
                bool need = !(bestv < H2MARG);          // also catches empty (NaN)
                unsigned m = __activemask();
                if (__any_sync(m, need)) {              // rare (~5e-5/point)
                    for (int t = 0; t < KK; t++) {
                        float4 c = sp->u.a.sc[t];
                        float dot = dot3_fma(p0, p1, p2, c.x, c.y, c.z);
                        float v = sqdist_combine(pn, dot, c.w);
                        u64 key = ((u64)float_ord(v) << 32) | sp->u.a.sk[t];
                        if (need) bkey = umin64(bkey, key);
                    }
                }
            }
            const int bi = (int)(bkey & 0xFFFFull);
            u64* sm = &g_isum[Wb][((size_t)b * KK + bi) * 3];
            atomicAdd(sm + 0, (u64)__double2ll_rn((double)p0 * FIXSCALE));
            atomicAdd(sm + 1, (u64)__double2ll_rn((double)p1 * FIXSCALE));
            atomicAdd(sm + 2, (u64)__double2ll_rn((double)p2 * FIXSCALE));
            atomicAdd(&g_icnt[Wb][b * KK + bi], 1);
        }
        batch_sync(b);
    }

    // ================= TOPK (in-block; reuses persistent sorted points) ======
    const int FB = NITS % 3;   // = 2
    if (tid == 0) sp->u.t.fbn = 0;

    {
        const int u = tid / TPC;          // local centroid 0..63
        const int j = tid % TPC;          // lane within group
        const int k = grp * NCB + u;
        float c0, c1, c2;
        load_centroid(FB, b, k, c0, c1, c2);
        const float cn = norm3_nofma(c0, c1, c2);
        const int cx = cellc(c0), cy = cellc(c1), cz = cellc(c2);
        const int xlo = cx > 0 ? cx - 1 : 0, xhi = cx < 5 ? cx + 1 : 5;
        const int ylo = cy > 0 ? cy - 1 : 0, yhi = cy < 5 ? cy + 1 : 5;
        const int zlo = cz > 0 ? cz - 1 : 0, zhi = cz < 5 ? cz + 1 : 5;

        u64 l[PP];
#pragma unroll
        for (int q = 0; q < PP; q++) l[q] = 0xFF800000FFFFFFFFull;  // ord(+inf)|idx_max
        float thresh = __int_as_float(0x7f800000);

        for (int z = zlo; z <= zhi; z++) {
            for (int y = ylo; y <= yhi; y++) {
                int row = (z * NC + y) * NC;
                int t0 = sp->startP[row + xlo];
                int t1 = sp->startP[row + xhi + 1];
                int t = t0 + j;
                for (; t + TPC < t1; t += 2 * TPC) {   // insert order preserved
                    float4 pa = sp->tp[t];
                    float4 pb = sp->tp[t + TPC];
                    float da = dot3_fma(c0, c1, c2, pa.x, pa.y, pa.z);
                    float db = dot3_fma(c0, c1, c2, pb.x, pb.y, pb.z);
                    float va = sqdist_combine(cn, da, pa.w);
                    float vb = sqdist_combine(cn, db, pb.w);
                    top8_insert(l, thresh, va, (unsigned)sp->tpi[t]);
                    top8_insert(l, thresh, vb, (unsigned)sp->tpi[t + TPC]);
                }
                if (t < t1) {
                    float4 p = sp->tp[t];
                    float dot = dot3_fma(c0, c1, c2, p.x, p.y, p.z);
                    float v = sqdist_combine(cn, dot, p.w);
                    top8_insert(l, thresh, v, (unsigned)sp->tpi[t]);
                }
            }
        }
#pragma unroll
        for (int q = 0; q < PP; q++) sp->u.t.part[u][j][q] = l[q];
    }
    __syncthreads();

    // ---- merge TPC partials per centroid -> g_sidx; flag fallbacks ----
    if (tid < NCB) {
        u64 a[PP];
#pragma unroll
        for (int q = 0; q < PP; q++) a[q] = sp->u.t.part[tid][0][q];
#pragma unroll
        for (int c = 1; c < TPC; c++) merge8(a, sp->u.t.part[tid][c]);
        int* gout = g_sidx[b * KK + grp * NCB + tid];
#pragma unroll
        for (int q = 0; q < PP; q++) gout[q] = (int)(a[q] & 0xFFFFu);
        float d7 = ord_inv((unsigned)(a[7] >> 32));
        if (!(d7 < H2MARG)) {
            int i = atomicAdd(&sp->u.t.fbn, 1);
            sp->u.t.fblist[i] = tid;
        }
    }
    __syncthreads();

    // ---- cooperative fallback: one warp per flagged centroid, exact full scan ----
    {
        const int warp = tid >> 5, lane = tid & 31;
        const int nfb = sp->u.t.fbn;
        for (int i = warp; i < nfb; i += 16) {
            int u = sp->u.t.fblist[i];
            int k = grp * NCB + u;
            float c0, c1, c2;
            load_centroid(FB, b, k, c0, c1, c2);
            float cn = norm3_nofma(c0, c1, c2);
            u64 l[PP];
#pragma unroll
            for (int q = 0; q < PP; q++) l[q] = 0xFF800000FFFFFFFFull;
            float thresh = __int_as_float(0x7f800000);
            for (int t = lane; t < SS; t += 32) {
                float4 p = sp->tp[t];
                float dot = dot3_fma(c0, c1, c2, p.x, p.y, p.z);
                float v = sqdist_combine(cn, dot, p.w);
                top8_insert(l, thresh, v, (unsigned)sp->tpi[t]);
            }
            // warp's own scratch: 32 of the (dead) 512 partial lists
            u64* reg = &sp->u.t.part[0][0][0] + (size_t)warp * 32 * PP;
#pragma unroll
            for (int q = 0; q < PP; q++) reg[lane * 8 + q] = l[q];
            __syncwarp();
            if (lane == 0) {
                u64 a[PP];
#pragma unroll
                for (int q = 0; q < PP; q++) a[q] = reg[q];
                for (int c = 1; c < 32; c++) merge8(a, &reg[c * 8]);
                int* gout = g_sidx[b * KK + k];
#pragma unroll
                for (int q = 0; q < PP; q++) gout[q] = (int)(a[q] & 0xFFFFu);
            }
            __syncwarp();
        }
    }
}

// ---------------- gather kernel: full-occupancy pure-bandwidth ----------------
// block = 8 (b,k) units x 64 float4 columns; thread = one output float4, 8 LDG.128
__global__ void __launch_bounds__(512)
gatherk(const float* __restrict__ x, float* __restrict__ out) {
    __shared__ int sidx[8][PP];
    const int tid = threadIdx.x;
    const int bk0 = blockIdx.x * 8;
    if (tid < 64)
        sidx[tid >> 3][tid & 7] = g_sidx[bk0 + (tid >> 3)][tid & 7];
    __syncthreads();

    const int u = tid >> 6;        // 0..7
    const int lane = tid & 63;     // float4 column
    const int bk = bk0 + u;
    const int b = bk >> 9;         // / KK
    const float4* xb4 = reinterpret_cast<const float4*>(x) + (size_t)b * SS * (FF / 4);
    const int* si = sidx[u];

    float acc0 = 0.f, acc1 = 0.f, acc2 = 0.f, acc3 = 0.f;
#pragma unroll
    for (int p = 0; p < 8; p++) {
        float4 v = __ldg(&xb4[(size_t)si[p] * (FF / 4) + lane]);
        acc0 += v.x; acc1 += v.y; acc2 += v.z; acc3 += v.w;
    }
    reinterpret_cast<float4*>(out)[(size_t)bk * (FF / 4) + lane] =
        make_float4(acc0 * 0.125f, acc1 * 0.125f, acc2 * 0.125f, acc3 * 0.125f);
}

// ---------------- launch ----------------
extern "C" void kernel_launch(void* const* d_in, const int* in_sizes, int n_in,
                              void* d_out, int out_size) {
    const float* x   = (const float*)d_in[0];   // (B,S,F) f32
    const float* pos = (const float*)d_in[1];   // (B,S,D) f32
    float* out = (float*)d_out;                 // (B,K,F) f32
    (void)in_sizes; (void)n_in; (void)out_size;

    cudaFuncSetAttribute(mega, cudaFuncAttributeMaxDynamicSharedMemorySize,
                         (int)sizeof(SP));
    mega<<<GRID, THREADS, sizeof(SP)>>>(pos);
    gatherk<<<BB * KK / 8, 512>>>(x, out);
}

// round 17
// speedup vs baseline: 1.0395x; 1.0395x over previous
#include <cuda_runtime.h>
#include <cstdint>

#define BB 16
#define SS 4096
#define FF 256
#define KK 512
#define PP 8
#define NITS 5
#define THREADS 512
#define BPB 8                 // blocks per batch
#define GRID (BB * BPB)       // 128
#define NCB 64                // centroids per block (topk/gather)
#define TPC 8                 // threads per centroid in topk
#define FIXSCALE 1099511627776.0   // 2^40
#define NC 6
#define NCELLS 216
#define H2MARG 0.0276778f     // (1/6)^2 - 1e-4 safety margin
#define ROWMARG 1e-4f         // row-bound safety margin

typedef unsigned long long u64;
typedef unsigned short u16;

// ---------------- device scratch ----------------
static __device__ u64 g_isum[3][BB * KK * 3];   // triple-buffered fixed-point sums
static __device__ int g_icnt[3][BB * KK];       // triple-buffered counts

struct Bar { unsigned cnt; unsigned phase; unsigned pad[30]; };  // 128B, own line
static __device__ Bar g_bars[BB];

// ---------------- dynamic smem layout ----------------
struct SP {
    float4 tp[SS];        // 64KB: batch points, cell-sorted (persistent)
    u16 tpi[SS];          // 8KB: original s of sorted point (persistent)
    int startP[257];      // point-cell starts (persistent)
    int wsums[8];         // scan scratch
    int cut[BPB + 1];     // cell-aligned block slice cuts
    union {
        struct {          // assign phase (~11KB)
            float4 sc[KK];      // cell-sorted centroids
            u16 sk[KK];         // original k
            int cntC[256];      // counters / cursors
            int startC[257];
        } a;
        struct {          // topk phase (~35KB)
            u64 part[NCB][TPC][PP];
            int sidx[NCB][PP];
            int fblist[NCB];
            int fbn;
        } t;
    } u;
};

// ---------------- FP helpers (reference-exact semantics) --------
__device__ __forceinline__ unsigned float_ord(float f) {
    unsigned u = __float_as_uint(f);
    return (u & 0x80000000u) ? ~u : (u | 0x80000000u);
}
__device__ __forceinline__ float ord_inv(unsigned u) {
    return __uint_as_float((u & 0x80000000u) ? (u & 0x7FFFFFFFu) : ~u);
}
__device__ __forceinline__ u64 umin64(u64 a, u64 b) { return a < b ? a : b; }
// mirrors jnp.sum(a*a,-1): elementwise mul then sequential reduce (no FMA contraction)
__device__ __forceinline__ float norm3_nofma(float a0, float a1, float a2) {
    return __fadd_rn(__fadd_rn(__fmul_rn(a0, a0), __fmul_rn(a1, a1)), __fmul_rn(a2, a2));
}
// ascending-d fma chain
__device__ __forceinline__ float dot3_fma(float a0, float a1, float a2,
                                          float b0, float b1, float b2) {
    return __fmaf_rn(a2, b2, __fmaf_rn(a1, b1, __fmul_rn(a0, b0)));
}
// (aa - 2*dot) + bb, reference grouping
__device__ __forceinline__ float sqdist_combine(float aa, float dot, float bb) {
    return __fadd_rn(__fmaf_rn(-2.0f, dot, aa), bb);
}
__device__ __forceinline__ int cellc(float x) {
    int i = (int)floorf(x * 6.0f);
    return i < 0 ? 0 : (i > 5 ? 5 : i);
}
// lower bound on squared (y,z)-distance from (p1,p2) to cell row (y,z)
__device__ __forceinline__ float row_bound2(int y, int z, float p1, float p2) {
    const float h = 1.0f / 6.0f;
    float ylo = y * h, yhi = (y + 1) * h;
    float zlo = z * h, zhi = (z + 1) * h;
    float dy = fmaxf(0.0f, fmaxf(ylo - p1, p1 - yhi));
    float dz = fmaxf(0.0f, fmaxf(zlo - p2, p2 - zhi));
    return dy * dy + dz * dz;
}

__device__ __forceinline__ void sort8_bitonic(u64 v[8]) {
#define CSWP(i, j) { u64 lo = umin64(v[i], v[j]); \
                     u64 hi = (v[i] < v[j]) ? v[j] : v[i]; \
                     v[i] = lo; v[j] = hi; }
    CSWP(0, 4) CSWP(1, 5) CSWP(2, 6) CSWP(3, 7)
    CSWP(0, 2) CSWP(1, 3) CSWP(4, 6) CSWP(5, 7)
    CSWP(0, 1) CSWP(2, 3) CSWP(4, 5) CSWP(6, 7)
#undef CSWP
}
__device__ __forceinline__ void merge8(u64 a[8], const u64 b[8]) {
    u64 m[8];
#pragma unroll
    for (int i = 0; i < 8; i++) m[i] = umin64(a[i], b[7 - i]);
    sort8_bitonic(m);
#pragma unroll
    for (int i = 0; i < 8; i++) a[i] = m[i];
}

// sorted-insert; <= lets equal-dist smaller-idx keys reach the key compare
__device__ __forceinline__ void top8_insert(u64 l[PP], float& thresh, float v, unsigned idx) {
    if (v <= thresh) {
        float vc = (v == 0.0f) ? 0.0f : v;   // canonicalize -0.0
        u64 key = ((u64)float_ord(vc) << 32) | idx;
        if (key < l[7]) {
            l[7] = key;
#pragma unroll
            for (int j = 7; j > 0; --j)
                if (l[j] < l[j - 1]) { u64 tt = l[j]; l[j] = l[j - 1]; l[j - 1] = tt; }
            thresh = ord_inv((unsigned)(l[7] >> 32));
        }
    }
}

// shfl-based 256-entry scan: counts in cnt[] -> starts in startArr[0..256],
// exclusive cursors written back into cnt[].
__device__ __forceinline__ void scan256(int* cnt, int* startArr, int* wsums, int tid) {
    int w = tid >> 5, lane = tid & 31;
    int orig = 0, v = 0;
    if (tid < 256) {
        orig = cnt[tid]; v = orig;
#pragma unroll
        for (int off = 1; off < 32; off <<= 1) {
            int n = __shfl_up_sync(0xFFFFFFFFu, v, off);
            if (lane >= off) v += n;
        }
        if (lane == 31) wsums[w] = v;
    }
    __syncthreads();
    if (tid < 8) {
        int s = wsums[tid];
#pragma unroll
        for (int off = 1; off < 8; off <<= 1) {
            int n = __shfl_up_sync(0xFFu, s, off);
            if (tid >= off) s += n;
        }
        wsums[tid] = s;
    }
    __syncthreads();
    if (tid < 256) {
        int incl = v + (w > 0 ? wsums[w - 1] : 0);
        startArr[tid + 1] = incl;
        cnt[tid] = incl - orig;       // exclusive prefix = scatter cursor
    }
    if (tid == 0) startArr[0] = 0;
    __syncthreads();
}

// ---------------- per-batch barrier (BPB blocks, all co-resident) ----
__device__ __forceinline__ void batch_sync(int b) {
    __syncthreads();
    if (threadIdx.x == 0) {
        __threadfence();
        unsigned gen = atomicAdd(&g_bars[b].phase, 0u);
        if (atomicAdd(&g_bars[b].cnt, 1u) == BPB - 1) {
            g_bars[b].cnt = 0;
            __threadfence();
            atomicAdd(&g_bars[b].phase, 1u);  // release
        } else {
            while (atomicAdd(&g_bars[b].phase, 0u) == gen) __nanosleep(32);
        }
        __threadfence();
    }
    __syncthreads();
}

__device__ __forceinline__ void load_centroid(int fb, int b, int k,
                                              float& c0, float& c1, float& c2) {
    int slot = b * KK + k;
    float cnt = (float)g_icnt[fb][slot];
    cnt = cnt > 1.0f ? cnt : 1.0f;
    c0 = __fdiv_rn((float)((double)(long long)g_isum[fb][3 * slot + 0] * (1.0 / FIXSCALE)), cnt);
    c1 = __fdiv_rn((float)((double)(long long)g_isum[fb][3 * slot + 1] * (1.0 / FIXSCALE)), cnt);
    c2 = __fdiv_rn((float)((double)(long long)g_isum[fb][3 * slot + 2] * (1.0 / FIXSCALE)), cnt);
}

// row visit order: own, faces, diagonals (result independent of order)
__device__ __constant__ int DZR[9] = {0, 0, 0, -1, 1, -1, -1, 1, 1};
__device__ __constant__ int DYR[9] = {0, -1, 1, 0, 0, -1, 1, -1, 1};

// ---------------- megakernel ----------------
__global__ void __launch_bounds__(THREADS, 1)
mega(const float* __restrict__ x, const float* __restrict__ pos, float* __restrict__ out) {
    extern __shared__ char smem_raw[];
    SP* sp = reinterpret_cast<SP*>(smem_raw);

    const int tid = threadIdx.x;
    const int blk = blockIdx.x;
    const int b = blk / BPB;           // batch
    const int grp = blk % BPB;         // group within batch

    // ---- init: zero buffer 1, batch-local (this block's 64 slots) ----
    if (tid < NCB) {
        int slot = b * KK + grp * NCB + tid;
        g_icnt[1][slot] = 0;
        g_isum[1][3 * slot + 0] = 0ull;
        g_isum[1][3 * slot + 1] = 0ull;
        g_isum[1][3 * slot + 2] = 0ull;
    }

    // ---- bin ALL 4096 batch points by cell, once (persistent tp/tpi/startP) ----
    if (tid < 256) sp->u.a.cntC[tid] = 0;
    __syncthreads();
#pragma unroll
    for (int j = 0; j < 8; j++) {
        int i = j * 512 + tid;
        const float* qp = pos + ((size_t)b * SS + i) * 3;
        int cell = (cellc(qp[2]) * NC + cellc(qp[1])) * NC + cellc(qp[0]);
        atomicAdd(&sp->u.a.cntC[cell], 1);
    }
    __syncthreads();
    scan256(sp->u.a.cntC, sp->startP, sp->wsums, tid);
#pragma unroll
    for (int j = 0; j < 8; j++) {
        int i = j * 512 + tid;
        const float* qp = pos + ((size_t)b * SS + i) * 3;
        float q0 = qp[0], q1 = qp[1], q2 = qp[2];
        int cell = (cellc(q2) * NC + cellc(q1)) * NC + cellc(q0);
        int slot = atomicAdd(&sp->u.a.cntC[cell], 1);
        sp->tp[slot] = make_float4(q0, q1, q2, norm3_nofma(q0, q1, q2));
        sp->tpi[slot] = (u16)i;
    }
    __syncthreads();
    // cell-aligned block cuts: cut[g] = startP[min{c : startP[c] >= g*512}]
    if (tid < BPB + 1) {
        int target = tid * (SS / BPB);
        int c = 0;
        while (c < NCELLS && sp->startP[c] < target) c++;
        sp->cut[tid] = sp->startP[c];
    }
    batch_sync(b);   // covers init-zero + cuts (all batch-local)

    // ================= K-MEANS: 5 iterations, one batch barrier each =========
    for (int it = 0; it < NITS; it++) {
        const int Rb = it % 3;
        const int Wb = (it + 1) % 3;
        const int Zb = (it + 2) % 3;

        // centroid k = tid
        float c0, c1, c2;
        if (it == 0) {
            const float* cp = pos + ((size_t)b * SS + tid) * 3;
            c0 = cp[0]; c1 = cp[1]; c2 = cp[2];
        } else {
            load_centroid(Rb, b, tid, c0, c1, c2);
        }
        const float cn = norm3_nofma(c0, c1, c2);
        const int ccell = (cellc(c2) * NC + cellc(c1)) * NC + cellc(c0);

        if (tid < 256) sp->u.a.cntC[tid] = 0;
        if (tid < NCB) {          // zero Z-buffer slice (batch-local)
            int slot = b * KK + grp * NCB + tid;
            g_icnt[Zb][slot] = 0;
            g_isum[Zb][3 * slot + 0] = 0ull;
            g_isum[Zb][3 * slot + 1] = 0ull;
            g_isum[Zb][3 * slot + 2] = 0ull;
        }
        __syncthreads();
        atomicAdd(&sp->u.a.cntC[ccell], 1);
        __syncthreads();
        scan256(sp->u.a.cntC, sp->u.a.startC, sp->wsums, tid);
        {
            int slot = atomicAdd(&sp->u.a.cntC[ccell], 1);
            sp->u.a.sc[slot] = make_float4(c0, c1, c2, cn);
            sp->u.a.sk[slot] = (u16)tid;
        }
        __syncthreads();

        // ---- assign with row-bound pruning ----
        for (int idx = sp->cut[grp] + tid; idx < sp->cut[grp + 1]; idx += THREADS) {
            float4 pt = sp->tp[idx];
            const float p0 = pt.x, p1 = pt.y, p2 = pt.z, pn = pt.w;
            const int pix = cellc(p0), piy = cellc(p1), piz = cellc(p2);
            const int xlo = pix > 0 ? pix - 1 : 0, xhi = pix < 5 ? pix + 1 : 5;

            u64 bkey = 0xFFFFFFFFFFFFFFFFull;
#pragma unroll
            for (int r = 0; r < 9; r++) {
                int z = piz + DZR[r], y = piy + DYR[r];
                bool valid = (z >= 0) && (z < NC) && (y >= 0) && (y < NC);
                if (r > 0 && valid) {
                    float dmin2 = row_bound2(y, z, p1, p2);
                    float bestv = ord_inv((unsigned)(bkey >> 32));
                    // skip iff provably all row candidates' v > bestv
                    // (NaN sentinel best -> comparison false -> never skip)
                    if (dmin2 - ROWMARG > bestv) valid = false;
                }
                if (valid) {
                    int row = (z * NC + y) * NC;
                    int t0 = sp->u.a.startC[row + xlo];
                    int t1 = sp->u.a.startC[row + xhi + 1];
                    int t = t0;
                    for (; t + 1 < t1; t += 2) {      // two independent chains
                        float4 ca = sp->u.a.sc[t];
                        float4 cb = sp->u.a.sc[t + 1];
                        float da = dot3_fma(p0, p1, p2, ca.x, ca.y, ca.z);
                        float db = dot3_fma(p0, p1, p2, cb.x, cb.y, cb.z);
                        float va = sqdist_combine(pn, da, ca.w);
                        float vb = sqdist_combine(pn, db, cb.w);
                        u64 ka = ((u64)float_ord(va) << 32) | sp->u.a.sk[t];
                        u64 kb = ((u64)float_ord(vb) << 32) | sp->u.a.sk[t + 1];
                        bkey = umin64(bkey, umin64(ka, kb));
                    }
                    if (t < t1) {
                        float4 c = sp->u.a.sc[t];
                        float dot = dot3_fma(p0, p1, p2, c.x, c.y, c.z);
                        float v = sqdist_combine(pn, dot, c.w);
                        bkey = umin64(bkey, ((u64)float_ord(v) << 32) | sp->u.a.sk[t]);
                    }
                }
            }
            {
                float bestv = ord_inv((unsigned)(bkey >> 32));
                bool need = !(bestv < H2MARG);          // also catches empty (NaN)
                unsigned m = __activemask();
                if (__any_sync(m, need)) {              // rare (~5e-5/point)
                    for (int t = 0; t < KK; t++) {
                        float4 c = sp->u.a.sc[t];
                        float dot = dot3_fma(p0, p1, p2, c.x, c.y, c.z);
                        float v = sqdist_combine(pn, dot, c.w);
                        u64 key = ((u64)float_ord(v) << 32) | sp->u.a.sk[t];
                        if (need) bkey = umin64(bkey, key);
                    }
                }
            }
            const int bi = (int)(bkey & 0xFFFFull);
            u64* sm = &g_isum[Wb][((size_t)b * KK + bi) * 3];
            atomicAdd(sm + 0, (u64)__double2ll_rn((double)p0 * FIXSCALE));
            atomicAdd(sm + 1, (u64)__double2ll_rn((double)p1 * FIXSCALE));
            atomicAdd(sm + 2, (u64)__double2ll_rn((double)p2 * FIXSCALE));
            atomicAdd(&g_icnt[Wb][b * KK + bi], 1);
        }
        batch_sync(b);
    }

    // ================= TOPK (in-block; reuses persistent sorted points) ======
    const int FB = NITS % 3;   // = 2
    if (tid == 0) sp->u.t.fbn = 0;

    {
        const int u = tid / TPC;          // local centroid 0..63
        const int j = tid % TPC;          // lane within group (quarter-warp)
        const int k = grp * NCB + u;
        float c0, c1, c2;
        load_centroid(FB, b, k, c0, c1, c2);
        const float cn = norm3_nofma(c0, c1, c2);
        const int cx = cellc(c0), cy = cellc(c1), cz = cellc(c2);
        const int xlo = cx > 0 ? cx - 1 : 0, xhi = cx < 5 ? cx + 1 : 5;

        u64 l[PP];
#pragma unroll
        for (int q = 0; q < PP; q++) l[q] = 0xFF800000FFFFFFFFull;  // ord(+inf)|idx_max
        float thresh = __int_as_float(0x7f800000);

#pragma unroll
        for (int r = 0; r < 9; r++) {
            int z = cz + DZR[r], y = cy + DYR[r];
            bool valid = (z >= 0) && (z < NC) && (y >= 0) && (y < NC);
            float dmin2 = 0.0f;
            if (r > 0 && valid) dmin2 = row_bound2(y, z, c1, c2);
            // d8 upper bound over the 8-thread group (uniform: every lane reaches)
            float tf = thresh;
            tf = fminf(tf, __shfl_xor_sync(0xFFFFFFFFu, tf, 1));
            tf = fminf(tf, __shfl_xor_sync(0xFFFFFFFFu, tf, 2));
            tf = fminf(tf, __shfl_xor_sync(0xFFFFFFFFu, tf, 4));
            if (r > 0 && valid && (dmin2 - ROWMARG > tf)) valid = false;
            if (valid) {
                int row = (z * NC + y) * NC;
                int t0 = sp->startP[row + xlo];
                int t1 = sp->startP[row + xhi + 1];
                int t = t0 + j;
                for (; t + TPC < t1; t += 2 * TPC) {   // per-thread order preserved
                    float4 pa = sp->tp[t];
                    float4 pb = sp->tp[t + TPC];
                    float da = dot3_fma(c0, c1, c2, pa.x, pa.y, pa.z);
                    float db = dot3_fma(c0, c1, c2, pb.x, pb.y, pb.z);
                    float va = sqdist_combine(cn, da, pa.w);
                    float vb = sqdist_combine(cn, db, pb.w);
                    top8_insert(l, thresh, va, (unsigned)sp->tpi[t]);
                    top8_insert(l, thresh, vb, (unsigned)sp->tpi[t + TPC]);
                }
                if (t < t1) {
                    float4 p = sp->tp[t];
                    float dot = dot3_fma(c0, c1, c2, p.x, p.y, p.z);
                    float v = sqdist_combine(cn, dot, p.w);
                    top8_insert(l, thresh, v, (unsigned)sp->tpi[t]);
                }
            }
        }
#pragma unroll
        for (int q = 0; q < PP; q++) sp->u.t.part[u][j][q] = l[q];
    }
    __syncthreads();

    // ---- merge TPC partials per centroid; flag fallbacks ----
    if (tid < NCB) {
        u64 a[PP];
#pragma unroll
        for (int q = 0; q < PP; q++) a[q] = sp->u.t.part[tid][0][q];
#pragma unroll
        for (int c = 1; c < TPC; c++) merge8(a, sp->u.t.part[tid][c]);
#pragma unroll
        for (int q = 0; q < PP; q++) sp->u.t.sidx[tid][q] = (int)(a[q] & 0xFFFFu);
        float d7 = ord_inv((unsigned)(a[7] >> 32));
        if (!(d7 < H2MARG)) {
            int i = atomicAdd(&sp->u.t.fbn, 1);
            sp->u.t.fblist[i] = tid;
        }
    }
    __syncthreads();

    // ---- cooperative fallback: one warp per flagged centroid, exact full scan ----
    {
        const int warp = tid >> 5, lane = tid & 31;
        const int nfb = sp->u.t.fbn;
        for (int i = warp; i < nfb; i += 16) {
            int u = sp->u.t.fblist[i];
            int k = grp * NCB + u;
            float c0, c1, c2;
            load_centroid(FB, b, k, c0, c1, c2);
            float cn = norm3_nofma(c0, c1, c2);
            u64 l[PP];
#pragma unroll
            for (int q = 0; q < PP; q++) l[q] = 0xFF800000FFFFFFFFull;
            float thresh = __int_as_float(0x7f800000);
            for (int t = lane; t < SS; t += 32) {
                float4 p = sp->tp[t];
                float dot = dot3_fma(c0, c1, c2, p.x, p.y, p.z);
                float v = sqdist_combine(cn, dot, p.w);
                top8_insert(l, thresh, v, (unsigned)sp->tpi[t]);
            }
            // warp's own scratch: 32 of the (dead) 512 partial lists
            u64* reg = &sp->u.t.part[0][0][0] + (size_t)warp * 32 * PP;
#pragma unroll
            for (int q = 0; q < PP; q++) reg[lane * 8 + q] = l[q];
            __syncwarp();
            if (lane == 0) {
                u64 a[PP];
#pragma unroll
                for (int q = 0; q < PP; q++) a[q] = reg[q];
                for (int c = 1; c < 32; c++) merge8(a, &reg[c * 8]);
#pragma unroll
                for (int q = 0; q < PP; q++) sp->u.t.sidx[u][q] = (int)(a[q] & 0xFFFFu);
            }
            __syncwarp();
        }
    }
    __syncthreads();

    // ---- gather-mean in float4: 8 teams of 64 threads, MLP=8 ----
    {
        const float4* xb4 = reinterpret_cast<const float4*>(x) + (size_t)b * SS * (FF / 4);
        float4* ob4 = reinterpret_cast<float4*>(out) + ((size_t)b * KK + grp * NCB) * (FF / 4);
        const int team = tid >> 6;     // 0..7
        const int lane64 = tid & 63;   // float4 column
#pragma unroll 2
        for (int uu = 0; uu < 8; uu++) {
            int u = team * 8 + uu;
            const int* si = sp->u.t.sidx[u];
            float acc0 = 0.f, acc1 = 0.f, acc2 = 0.f, acc3 = 0.f;
#pragma unroll
            for (int p = 0; p < 8; p++) {
                float4 v = __ldg(&xb4[(size_t)si[p] * (FF / 4) + lane64]);
                acc0 += v.x; acc1 += v.y; acc2 += v.z; acc3 += v.w;
            }
            ob4[(size_t)u * (FF / 4) + lane64] =
                make_float4(acc0 * 0.125f, acc1 * 0.125f, acc2 * 0.125f, acc3 * 0.125f);
        }
    }
}

// ---------------- launch ----------------
extern "C" void kernel_launch(void* const* d_in, const int* in_sizes, int n_in,
                              void* d_out, int out_size) {
    const float* x   = (const float*)d_in[0];   // (B,S,F) f32
    const float* pos = (const float*)d_in[1];   // (B,S,D) f32
    float* out = (float*)d_out;                 // (B,K,F) f32
    (void)in_sizes; (void)n_in; (void)out_size;

    cudaFuncSetAttribute(mega, cudaFuncAttributeMaxDynamicSharedMemorySize,
                         (int)sizeof(SP));
    mega<<<GRID, THREADS, sizeof(SP)>>>(x, pos, out);
}